// round 16
// baseline (speedup 1.0000x reference)
#include <cuda_runtime.h>
#include <cuda_bf16.h>
#include <math.h>
#include <stdint.h>

// Problem dims (fixed)
#define B_ 64
#define D_ 512
#define M_ 1024
#define L_ 256
#define KK_ 30

typedef __nv_bfloat16 bf16;

// ===================== device scratch =========================================
__device__ bf16 g_Wv_hi[32 * D_];
__device__ bf16 g_Wv_lo[32 * D_];
__device__ bf16 g_Wq_hi[32 * D_];
__device__ bf16 g_Wq_lo[32 * D_];
__device__ bf16 g_WqQ_hi[(long)B_ * 32 * L_];
__device__ bf16 g_WqQ_lo[(long)B_ * 32 * L_];
__device__ float g_WqQ_f[(long)B_ * 32 * L_];
__device__ bf16 g_P_hi[(long)B_ * 32 * D_];
__device__ bf16 g_P_lo[(long)B_ * 32 * D_];
__device__ bf16 g_Yv_hi[(long)B_ * 32 * D_];
__device__ bf16 g_Yv_lo[(long)B_ * 32 * D_];
__device__ bf16 g_WvV_hi[(long)B_ * 32 * M_];
__device__ bf16 g_WvV_lo[(long)B_ * 32 * M_];
__device__ float g_WvV_f[(long)B_ * 32 * M_];
__device__ bf16 g_Yq_hi[(long)B_ * 32 * D_];
__device__ bf16 g_Yq_lo[(long)B_ * 32 * D_];
__device__ bf16 g_R_hi[(long)B_ * 32 * D_];
__device__ bf16 g_R_lo[(long)B_ * 32 * D_];
__device__ float g_zv[B_ * M_];
__device__ float g_zq[B_ * L_];
__device__ float g_v1[B_ * D_];
__device__ float g_q1[B_ * D_];

// ===================== helpers ================================================
__device__ __forceinline__ uint32_t s2u(const void* p) {
    return (uint32_t)__cvta_generic_to_shared(p);
}
__device__ __forceinline__ void cp16(uint32_t dst, const void* src) {
    asm volatile("cp.async.cg.shared.global [%0], [%1], 16;" :: "r"(dst), "l"(src));
}
__device__ __forceinline__ void cp_commit() { asm volatile("cp.async.commit_group;"); }
__device__ __forceinline__ void cp_wait0()  { asm volatile("cp.async.wait_group 0;"); }

__device__ __forceinline__ void ldsm4(uint32_t* r, uint32_t addr) {
    asm volatile("ldmatrix.sync.aligned.m8n8.x4.shared.b16 {%0,%1,%2,%3}, [%4];"
                 : "=r"(r[0]), "=r"(r[1]), "=r"(r[2]), "=r"(r[3]) : "r"(addr));
}
__device__ __forceinline__ void ldsm4t(uint32_t* r, uint32_t addr) {
    asm volatile("ldmatrix.sync.aligned.m8n8.x4.trans.shared.b16 {%0,%1,%2,%3}, [%4];"
                 : "=r"(r[0]), "=r"(r[1]), "=r"(r[2]), "=r"(r[3]) : "r"(addr));
}
__device__ __forceinline__ void mma_bf(float* d, const uint32_t* a, const uint32_t* b) {
    asm volatile(
        "mma.sync.aligned.m16n8k16.row.col.f32.bf16.bf16.f32 "
        "{%0,%1,%2,%3}, {%4,%5,%6,%7}, {%8,%9}, {%0,%1,%2,%3};"
        : "+f"(d[0]), "+f"(d[1]), "+f"(d[2]), "+f"(d[3])
        : "r"(a[0]), "r"(a[1]), "r"(a[2]), "r"(a[3]), "r"(b[0]), "r"(b[1]));
}
__device__ __forceinline__ void split_bf(float x, bf16& h, bf16& l) {
    h = __float2bfloat16(x);
    l = __float2bfloat16(x - __bfloat162float(h));
}

// smem layout constants (bytes) -- 64-row m-tiles, 128-thread CTAs
#define A_BUF 5120u      // AN: 64 rows x 80B ; TRA: 32 rows x 144B (4608 <= slot)
#define B_BUF 2560u      // 32 x 40 bf16
#define BS_OFF 20480u    // after 4 A slots
#define CST 132          // epilogue staging n-stride (floats)
#define SMEM_SZ (int)(BS_OFF + 4 * B_BUF + 128)   // 30848

// ===================== weight pad conversion ==================================
__global__ void conv_pad(const float* __restrict__ Wv, bf16* __restrict__ Vh, bf16* __restrict__ Vl,
                         const float* __restrict__ Wq, bf16* __restrict__ Qh, bf16* __restrict__ Ql)
{
    int idx = blockIdx.x * blockDim.x + threadIdx.x;
    if (idx >= 32 * D_) return;
    int k = idx / D_, d = idx % D_;
    float a = (k < KK_) ? Wv[k * D_ + d] : 0.f;
    float b = (k < KK_) ? Wq[k * D_ + d] : 0.f;
    bf16 h, l;
    split_bf(a, h, l); Vh[idx] = h; Vl[idx] = l;
    split_bf(b, h, l); Qh[idx] = h; Ql[idx] = l;
}

// ===================== HMMA GEMM core (R10/R15 pipeline, NB=1) ================
// Ct[64-row m-tile of Nbig][32] = A(fp32, converted on the fly) x S[32,Kd]^T
struct GJob {
    const float* A;        // fp32 big operand
    int lda; long sA;
    const bf16 *Bh, *Bl;   // small operand [32][Kd] bf16 hi/lo
    long sB;
    bf16 *Ch, *Cl;         // out [b][32][Nbig] (EPI 0/1)
    float* Cf;             // EPI1: fp32 out; EPI3: fp32 X in
    const float* w;        // logits weights (EPI3)
    float* z;              // logits out [b][Nbig] (EPI3)
    int Nbig, Kd;
};

// EPI: 0 = hi/lo out; 1 = hi/lo + fp32 out; 3 = logits(acc + fp32 X), no C out
template<int EPI, bool TRA>
__device__ __forceinline__ void gemm_core(const GJob& j, int tile)
{
    extern __shared__ char smem[];
    const uint32_t sb = s2u(smem);
    float* smw = (float*)(smem + BS_OFF + 4 * B_BUF);

    const int tid = threadIdx.x;
    const int w = tid >> 5, lane = tid & 31;
    const int b = blockIdx.y;
    const int m0 = tile * 64;

    const float* Ab = j.A + (long)b * j.sA;
    const bf16* Bb[2] = { j.Bh + (long)b * j.sB, j.Bl + (long)b * j.sB };

    if (EPI == 3 && tid < KK_) smw[tid] = j.w[tid];

    // A gmem addressing (16 floats per thread per 32-k tile)
    const float* aptr = TRA
        ? (Ab + (long)(tid >> 2) * j.lda + m0 + (tid & 3) * 16)
        : (Ab + (long)(m0 + (tid >> 1)) * j.lda + (tid & 1) * 16);
    const uint32_t aSts = TRA ? (uint32_t)((tid >> 2) * 144 + (tid & 3) * 32)
                              : (uint32_t)((tid >> 1) * 80 + (tid & 1) * 32);

    // B staging indices: 32 rows x 4 cols of 16B, both hl per thread
    const int br = tid >> 2, bc = tid & 3;

    const int T = j.Kd / 32;
    float4 fr[4];

    auto loadA = [&](int t) {
        const float* p = TRA ? (aptr + (long)t * 32 * j.lda) : (aptr + t * 32);
        fr[0] = *(const float4*)p;
        fr[1] = *(const float4*)(p + 4);
        fr[2] = *(const float4*)(p + 8);
        fr[3] = *(const float4*)(p + 12);
    };
    auto stsA = [&](int s) {
        uint32_t hp[8], lp[8];
        const float* f = (const float*)fr;
#pragma unroll
        for (int i = 0; i < 8; i++) {
            bf16 h0, l0, h1, l1;
            split_bf(f[2 * i], h0, l0);
            split_bf(f[2 * i + 1], h1, l1);
            hp[i] = (uint32_t)*(uint16_t*)&h0 | ((uint32_t)*(uint16_t*)&h1 << 16);
            lp[i] = (uint32_t)*(uint16_t*)&l0 | ((uint32_t)*(uint16_t*)&l1 << 16);
        }
        char* d0 = smem + (s * 2 + 0) * A_BUF + aSts;
        char* d1 = smem + (s * 2 + 1) * A_BUF + aSts;
        *(uint4*)d0        = make_uint4(hp[0], hp[1], hp[2], hp[3]);
        *(uint4*)(d0 + 16) = make_uint4(hp[4], hp[5], hp[6], hp[7]);
        *(uint4*)d1        = make_uint4(lp[0], lp[1], lp[2], lp[3]);
        *(uint4*)(d1 + 16) = make_uint4(lp[4], lp[5], lp[6], lp[7]);
    };
    auto stageB = [&](int t) {
        const int s = t & 1;
#pragma unroll
        for (int hl = 0; hl < 2; hl++) {
            uint32_t dst = sb + BS_OFF + (uint32_t)((s * 2 + hl) * B_BUF)
                         + br * 80 + bc * 16;
            cp16(dst, Bb[hl] + (long)br * j.Kd + t * 32 + bc * 8);
        }
        cp_commit();
    };

    // ldmatrix lane addressing
    const uint32_t aLane = TRA
        ? (uint32_t)((((lane & 7) + 8 * (lane >> 4)) * 144) + (w * 16 + ((lane >> 3) & 1) * 8) * 2)
        : (uint32_t)((w * 16 + (lane & 15)) * 80 + (lane >> 4) * 16);
    const uint32_t aKs = TRA ? 2304u : 32u;
    const uint32_t bLaneRow = (uint32_t)((((lane >> 4) & 1) * 8 + (lane & 7)) * 80
                                         + ((lane >> 3) & 1) * 16);

    float acc[4][4];
#pragma unroll
    for (int nt = 0; nt < 4; nt++)
#pragma unroll
        for (int r = 0; r < 4; r++) acc[nt][r] = 0.f;

    stageB(0);
    loadA(0);

    for (int t = 0; t < T; t++) {
        const int s = t & 1;
        cp_wait0();
        __syncthreads();

        stsA(s);
        if (t + 1 < T) { stageB(t + 1); loadA(t + 1); }
        __syncthreads();

        const uint32_t aH = sb + (uint32_t)((s * 2 + 0) * A_BUF) + aLane;
        const uint32_t aL = aH + A_BUF;

#pragma unroll
        for (int ks = 0; ks < 2; ks++) {
            uint32_t ah[4], al[4];
            if (TRA) { ldsm4t(ah, aH + ks * aKs); ldsm4t(al, aL + ks * aKs); }
            else     { ldsm4 (ah, aH + ks * aKs); ldsm4 (al, aL + ks * aKs); }
#pragma unroll
            for (int p = 0; p < 2; p++) {
                uint32_t bbase = sb + BS_OFF + (uint32_t)((s * 2 + 0) * B_BUF)
                    + (uint32_t)(p * 16 * 80) + bLaneRow + ks * 32;
                uint32_t bh[4], bl[4];
                ldsm4(bh, bbase);
                ldsm4(bl, bbase + B_BUF);
                mma_bf(acc[2 * p],     ah, &bh[0]);
                mma_bf(acc[2 * p],     ah, &bl[0]);
                mma_bf(acc[2 * p],     al, &bh[0]);
                mma_bf(acc[2 * p + 1], ah, &bh[2]);
                mma_bf(acc[2 * p + 1], ah, &bl[2]);
                mma_bf(acc[2 * p + 1], al, &bh[2]);
            }
        }
    }

    // ---------------- epilogue: stage accs in smem (reuses A region) ---------
    __syncthreads();
    float* Cs = (float*)smem;
    {
        const int g = lane >> 2, cc = lane & 3;
        const int m_l = w * 16 + g;
#pragma unroll
        for (int nt = 0; nt < 4; nt++) {
            int n0 = nt * 8 + cc * 2;
            Cs[(n0 + 0) * CST + m_l]     = acc[nt][0];
            Cs[(n0 + 1) * CST + m_l]     = acc[nt][1];
            Cs[(n0 + 0) * CST + m_l + 8] = acc[nt][2];
            Cs[(n0 + 1) * CST + m_l + 8] = acc[nt][3];
        }
    }
    __syncthreads();

    if (EPI != 3) {
#pragma unroll
        for (int it = 0; it < 4; it++) {
            int q = tid + it * 128;
            int n = q >> 4, m4 = (q & 15) * 4;
            float4 v = *(float4*)&Cs[n * CST + m4];
            bf16 h0, l0, h1, l1, h2, l2, h3, l3;
            split_bf(v.x, h0, l0); split_bf(v.y, h1, l1);
            split_bf(v.z, h2, l2); split_bf(v.w, h3, l3);
            long o = ((long)b * 32 + n) * j.Nbig + m0 + m4;
            *(uint2*)(j.Ch + o) = make_uint2(
                ((uint32_t)*(uint16_t*)&h0) | ((uint32_t)*(uint16_t*)&h1 << 16),
                ((uint32_t)*(uint16_t*)&h2) | ((uint32_t)*(uint16_t*)&h3 << 16));
            *(uint2*)(j.Cl + o) = make_uint2(
                ((uint32_t)*(uint16_t*)&l0) | ((uint32_t)*(uint16_t*)&l1 << 16),
                ((uint32_t)*(uint16_t*)&l2) | ((uint32_t)*(uint16_t*)&l3 << 16));
            if (EPI == 1) *(float4*)(j.Cf + o) = v;
        }
    } else {
        if (tid < 64) {
            const float* X = j.Cf + (long)b * 32 * j.Nbig + m0 + tid;
            float zacc = 0.f;
#pragma unroll
            for (int k = 0; k < KK_; k++)
                zacc += smw[k] * tanhf(Cs[k * CST + tid] + X[(long)k * j.Nbig]);
            j.z[(long)b * j.Nbig + m0 + tid] = zacc;
        }
    }
}

// Two independent GEMMs in one launch (per-SM CTA interleaving)
template<int E0, bool T0, int E1, bool T1>
__global__ void __launch_bounds__(128)
pair_gemm(GJob j0, GJob j1, int tiles0)
{
    if ((int)blockIdx.x < tiles0) gemm_core<E0, T0>(j0, blockIdx.x);
    else                          gemm_core<E1, T1>(j1, blockIdx.x - tiles0);
}

// ===================== tail kernels (R10 originals) ============================
__global__ void softmax_kernel(float* __restrict__ z, int n)
{
    const int b = blockIdx.x;
    float* row = z + (long)b * n;
    __shared__ float red[256];
    const int tid = threadIdx.x;

    float mx = -1e30f;
    for (int i = tid; i < n; i += 256) mx = fmaxf(mx, row[i]);
    red[tid] = mx; __syncthreads();
    for (int s = 128; s > 0; s >>= 1) {
        if (tid < s) red[tid] = fmaxf(red[tid], red[tid + s]);
        __syncthreads();
    }
    mx = red[0]; __syncthreads();

    float sum = 0.f;
    for (int i = tid; i < n; i += 256) {
        float e = expf(row[i] - mx);
        row[i] = e;
        sum += e;
    }
    red[tid] = sum; __syncthreads();
    for (int s = 128; s > 0; s >>= 1) {
        if (tid < s) red[tid] += red[tid + s];
        __syncthreads();
    }
    float inv = 1.f / red[0];
    for (int i = tid; i < n; i += 256) row[i] *= inv;
}

__global__ void pool_v_kernel(const float* __restrict__ V,
                              const float* __restrict__ a,
                              float* __restrict__ v1)
{
    const int b = blockIdx.y;
    const int warp = threadIdx.x >> 5;
    const int lane = threadIdx.x & 31;
    const int d = blockIdx.x * 8 + warp;
    const float4* vr = reinterpret_cast<const float4*>(V + ((long)b * D_ + d) * M_);
    const float4* ar = reinterpret_cast<const float4*>(a + (long)b * M_);
    float acc = 0.f;
#pragma unroll
    for (int i = 0; i < M_ / 128; i++) {
        float4 v = vr[i * 32 + lane];
        float4 w = ar[i * 32 + lane];
        acc += v.x * w.x + v.y * w.y + v.z * w.z + v.w * w.w;
    }
#pragma unroll
    for (int o = 16; o > 0; o >>= 1) acc += __shfl_down_sync(0xffffffffu, acc, o);
    if (lane == 0) v1[b * D_ + d] = acc;
}

__global__ void pool_q_kernel(const float* __restrict__ Q,
                              const float* __restrict__ a,
                              float* __restrict__ q1)
{
    const int b = blockIdx.x;
    __shared__ float as[L_];
    for (int i = threadIdx.x; i < L_; i += blockDim.x) as[i] = a[b * L_ + i];
    __syncthreads();
    const int d = threadIdx.x;
    const float* qb = Q + (long)b * L_ * D_;
    float acc = 0.f;
#pragma unroll 8
    for (int l = 0; l < L_; l++) acc += as[l] * qb[(long)l * D_ + d];
    q1[b * D_ + d] = acc;
}

__global__ void bcast_kernel(float4* __restrict__ out,
                             const float4* __restrict__ src,
                             int rows)
{
    const long total4 = (long)B_ * rows * (D_ / 4);
    long i = (long)blockIdx.x * blockDim.x + threadIdx.x;
    if (i >= total4) return;
    int d4 = (int)(i % (D_ / 4));
    long br = i / (D_ / 4);
    int b = (int)(br / rows);
    out[i] = __ldg(&src[(long)b * (D_ / 4) + d4]);
}

// ===================== launch =================================================
extern "C" void kernel_launch(void* const* d_in, const int* in_sizes, int n_in,
                              void* d_out, int out_size)
{
    const float* V   = (const float*)d_in[0];  // [B, D, M]
    const float* Q   = (const float*)d_in[1];  // [B, L, D]
    const float* W_b = (const float*)d_in[2];  // [D, D]
    const float* W_v = (const float*)d_in[3];  // [K, D]
    const float* W_q = (const float*)d_in[4];  // [K, D]
    const float* whv = (const float*)d_in[5];  // [K]
    const float* whq = (const float*)d_in[6];  // [K]
    float* out = (float*)d_out;

    bf16 *pWv_h, *pWv_l, *pWq_h, *pWq_l;
    bf16 *pWqQ_h, *pWqQ_l, *pP_h, *pP_l, *pYv_h, *pYv_l;
    bf16 *pWvV_h, *pWvV_l, *pYq_h, *pYq_l, *pR_h, *pR_l;
    float *pWqQ_f, *pWvV_f, *p_zv, *p_zq, *p_v1, *p_q1;
    cudaGetSymbolAddress((void**)&pWv_h, g_Wv_hi);  cudaGetSymbolAddress((void**)&pWv_l, g_Wv_lo);
    cudaGetSymbolAddress((void**)&pWq_h, g_Wq_hi);  cudaGetSymbolAddress((void**)&pWq_l, g_Wq_lo);
    cudaGetSymbolAddress((void**)&pWqQ_h, g_WqQ_hi); cudaGetSymbolAddress((void**)&pWqQ_l, g_WqQ_lo);
    cudaGetSymbolAddress((void**)&pWqQ_f, g_WqQ_f);
    cudaGetSymbolAddress((void**)&pP_h, g_P_hi);    cudaGetSymbolAddress((void**)&pP_l, g_P_lo);
    cudaGetSymbolAddress((void**)&pYv_h, g_Yv_hi);  cudaGetSymbolAddress((void**)&pYv_l, g_Yv_lo);
    cudaGetSymbolAddress((void**)&pWvV_h, g_WvV_hi); cudaGetSymbolAddress((void**)&pWvV_l, g_WvV_lo);
    cudaGetSymbolAddress((void**)&pWvV_f, g_WvV_f);
    cudaGetSymbolAddress((void**)&pYq_h, g_Yq_hi);  cudaGetSymbolAddress((void**)&pYq_l, g_Yq_lo);
    cudaGetSymbolAddress((void**)&pR_h, g_R_hi);    cudaGetSymbolAddress((void**)&pR_l, g_R_lo);
    cudaGetSymbolAddress((void**)&p_zv, g_zv);      cudaGetSymbolAddress((void**)&p_zq, g_zq);
    cudaGetSymbolAddress((void**)&p_v1, g_v1);      cudaGetSymbolAddress((void**)&p_q1, g_q1);

    cudaFuncSetAttribute(pair_gemm<1, false, 1, true>,
                         cudaFuncAttributeMaxDynamicSharedMemorySize, SMEM_SZ);
    cudaFuncSetAttribute(pair_gemm<0, true, 0, false>,
                         cudaFuncAttributeMaxDynamicSharedMemorySize, SMEM_SZ);
    cudaFuncSetAttribute(pair_gemm<3, true, 3, false>,
                         cudaFuncAttributeMaxDynamicSharedMemorySize, SMEM_SZ);

    // fork/join machinery (host objects only)
    cudaStream_t s2;
    cudaEvent_t evFork, evJoin;
    cudaStreamCreateWithFlags(&s2, cudaStreamNonBlocking);
    cudaEventCreateWithFlags(&evFork, cudaEventDisableTiming);
    cudaEventCreateWithFlags(&evJoin, cudaEventDisableTiming);

    conv_pad<<<(32 * D_ + 255) / 256, 256>>>(W_v, pWv_h, pWv_l, W_q, pWq_h, pWq_l);

    const long sQ = (long)L_ * D_;
    const long sV = (long)D_ * M_;
    GJob j0, j1;

    // P1: K1 (AN,EPI1): WqQ = Wq x Q^T, A=Q [L][D]
    //  ∥  K4 (TRA,EPI1): WvV = Wv x V, A=V^T (lda=M)
    j0 = { Q, D_, sQ, pWq_h, pWq_l, 0, pWqQ_h, pWqQ_l, pWqQ_f,
           nullptr, nullptr, L_, D_ };
    j1 = { V, M_, sV, pWv_h, pWv_l, 0, pWvV_h, pWvV_l, pWvV_f,
           nullptr, nullptr, M_, D_ };
    pair_gemm<1, false, 1, true><<<dim3(L_/64 + M_/64, B_), 128, SMEM_SZ>>>(
        j0, j1, L_ / 64);

    // P2: K2 (TRA,EPI0): P = WqQ x Q, A=Q^T (lda=D), Kd=L
    //  ∥  K6 (AN, EPI0): Yq = WvV x V^T, A=V [D][M], Kd=M
    j0 = { Q, D_, sQ, pWqQ_h, pWqQ_l, (long)32 * L_, pP_h, pP_l, nullptr,
           nullptr, nullptr, D_, L_ };
    j1 = { V, M_, sV, pWvV_h, pWvV_l, (long)32 * M_, pYq_h, pYq_l, nullptr,
           nullptr, nullptr, D_, M_ };
    pair_gemm<0, true, 0, false><<<dim3(2 * (D_/64), B_), 128, SMEM_SZ>>>(
        j0, j1, D_ / 64);

    // P3: K3 (TRA,EPI0): Yv = P x Wb, A=Wb^T (no batch)
    //  ∥  K7 (AN, EPI0): R = Yq x Wb^T, A=Wb (no batch)
    j0 = { W_b, D_, 0, pP_h, pP_l, (long)32 * D_, pYv_h, pYv_l, nullptr,
           nullptr, nullptr, D_, D_ };
    j1 = { W_b, D_, 0, pYq_h, pYq_l, (long)32 * D_, pR_h, pR_l, nullptr,
           nullptr, nullptr, D_, D_ };
    pair_gemm<0, true, 0, false><<<dim3(2 * (D_/64), B_), 128, SMEM_SZ>>>(
        j0, j1, D_ / 64);

    // P4: K5' (TRA,EPI3): z_v = sum_k w tanh(WvV_f + Yv x V), A=V^T, B=Yv
    //  ∥  K8  (AN, EPI3): z_q = sum_k w tanh(WqQ_f + R x Q^T), A=Q, B=R
    j0 = { V, M_, sV, pYv_h, pYv_l, (long)32 * D_, nullptr, nullptr, pWvV_f,
           whv, p_zv, M_, D_ };
    j1 = { Q, D_, sQ, pR_h, pR_l, (long)32 * D_, nullptr, nullptr, pWqQ_f,
           whq, p_zq, L_, D_ };
    pair_gemm<3, true, 3, false><<<dim3(M_/64 + L_/64, B_), 128, SMEM_SZ>>>(
        j0, j1, M_ / 64);

    // ---- fork: q-tail on s2, v-tail on default
    cudaEventRecord(evFork, 0);
    cudaStreamWaitEvent(s2, evFork, 0);

    // q-tail on s2
    softmax_kernel<<<B_, 256, 0, s2>>>(p_zq, L_);
    pool_q_kernel<<<B_, 512, 0, s2>>>(Q, p_zq, p_q1);
    {
        long n4q = (long)B_ * L_ * (D_ / 4);
        float* out_q = out + (long)B_ * M_ * D_;
        bcast_kernel<<<(unsigned)((n4q + 255) / 256), 256, 0, s2>>>(
            (float4*)out_q, (const float4*)p_q1, L_);
    }

    // v-tail on default stream
    softmax_kernel<<<B_, 256>>>(p_zv, M_);
    {
        dim3 grid(D_ / 8, B_);
        pool_v_kernel<<<grid, 256>>>(V, p_zv, p_v1);
    }
    {
        long n4v = (long)B_ * M_ * (D_ / 4);
        bcast_kernel<<<(unsigned)((n4v + 255) / 256), 256>>>(
            (float4*)out, (const float4*)p_v1, M_);
    }

    // ---- join
    cudaEventRecord(evJoin, s2);
    cudaStreamWaitEvent(0, evJoin, 0);

    cudaEventDestroy(evFork);
    cudaEventDestroy(evJoin);
    cudaStreamDestroy(s2);
}